// round 1
// baseline (speedup 1.0000x reference)
#include <cuda_runtime.h>
#include <cuda_bf16.h>

// Problem: cosine similarity matrix
//   x, y: [B=8, N=2048, D=512] fp32
//   out[b,n,m] = dot(x[b,n,:], y[b,m,:]) / max(||x[b,n]|| * ||y[b,m]||, 1e-8)
//
// Plan: norms kernel (warp per row) -> tiled SGEMM (128x128x16, 8x8 per thread)
// with fused cosine epilogue. Scratch norms live in __device__ globals
// (allocation-free, graph-capturable).

#define Bq 8
#define Nq 2048
#define Dq 512
#define EPSq 1e-8f

// scratch for norms: 8*2048 floats each
__device__ float g_xn[Bq * Nq];
__device__ float g_yn[Bq * Nq];

// ---------------------------------------------------------------------------
// Norm kernel: one warp per row, vectorized float4 loads, shfl reduction.
// ---------------------------------------------------------------------------
__global__ void __launch_bounds__(256) norms_kernel(const float* __restrict__ X,
                                                    const float* __restrict__ Y) {
    int warp_id = blockIdx.x * (blockDim.x >> 5) + (threadIdx.x >> 5);
    int lane = threadIdx.x & 31;
    if (warp_id >= Bq * Nq) return;

    const float4* px = reinterpret_cast<const float4*>(X + (size_t)warp_id * Dq);
    const float4* py = reinterpret_cast<const float4*>(Y + (size_t)warp_id * Dq);

    float sx = 0.f, sy = 0.f;
#pragma unroll
    for (int i = lane; i < Dq / 4; i += 32) {
        float4 a = px[i];
        sx = fmaf(a.x, a.x, sx); sx = fmaf(a.y, a.y, sx);
        sx = fmaf(a.z, a.z, sx); sx = fmaf(a.w, a.w, sx);
        float4 b = py[i];
        sy = fmaf(b.x, b.x, sy); sy = fmaf(b.y, b.y, sy);
        sy = fmaf(b.z, b.z, sy); sy = fmaf(b.w, b.w, sy);
    }
#pragma unroll
    for (int off = 16; off > 0; off >>= 1) {
        sx += __shfl_xor_sync(0xFFFFFFFFu, sx, off);
        sy += __shfl_xor_sync(0xFFFFFFFFu, sy, off);
    }
    if (lane == 0) {
        g_xn[warp_id] = sqrtf(sx);
        g_yn[warp_id] = sqrtf(sy);
    }
}

// ---------------------------------------------------------------------------
// Tiled SGEMM with fused cosine epilogue.
//   C[n,m] = sum_d X[n,d] * Y[m,d]   (both K-major, so GEMM-NT)
// Block: 256 threads = 16x16 thread grid, each thread owns an 8x8 micro-tile.
// Tile: BM=128 (n), BN=128 (m), BK=16.
// ---------------------------------------------------------------------------
#define BM 128
#define BN 128
#define BK 16
#define TM 8
#define TN 8

__global__ void __launch_bounds__(256, 2) cosine_gemm_kernel(
    const float* __restrict__ X, const float* __restrict__ Y,
    float* __restrict__ out) {
    const int b = blockIdx.z;
    const int tileN = blockIdx.y;  // block of n (rows of x)
    const int tileM = blockIdx.x;  // block of m (rows of y)

    const float* Xb = X + (size_t)b * Nq * Dq + (size_t)tileN * BM * Dq;
    const float* Yb = Y + (size_t)b * Nq * Dq + (size_t)tileM * BN * Dq;

    __shared__ float As[BK][BM];  // As[k][n] (transposed on load)
    __shared__ float Bs[BK][BN];  // Bs[k][m]

    const int tid = threadIdx.x;        // 0..255
    const int tr = tid >> 4;            // 0..15 -> n direction
    const int tc = tid & 15;            // 0..15 -> m direction

    float acc[TM][TN];
#pragma unroll
    for (int i = 0; i < TM; i++)
#pragma unroll
        for (int j = 0; j < TN; j++) acc[i][j] = 0.f;

    // Load indexing: per k-tile we fetch 128 rows x 16 k = 512 float4 per
    // operand; thread t fetches float4 index {t, t+256}.
    for (int k0 = 0; k0 < Dq; k0 += BK) {
#pragma unroll
        for (int li = 0; li < 2; li++) {
            int idx = tid + li * 256;     // 0..511
            int row = idx >> 2;           // 0..127
            int c4 = idx & 3;             // which float4 of the 16-wide k slab
            float4 xa = *reinterpret_cast<const float4*>(
                Xb + (size_t)row * Dq + k0 + c4 * 4);
            float4 ya = *reinterpret_cast<const float4*>(
                Yb + (size_t)row * Dq + k0 + c4 * 4);
            As[c4 * 4 + 0][row] = xa.x;
            As[c4 * 4 + 1][row] = xa.y;
            As[c4 * 4 + 2][row] = xa.z;
            As[c4 * 4 + 3][row] = xa.w;
            Bs[c4 * 4 + 0][row] = ya.x;
            Bs[c4 * 4 + 1][row] = ya.y;
            Bs[c4 * 4 + 2][row] = ya.z;
            Bs[c4 * 4 + 3][row] = ya.w;
        }
        __syncthreads();

#pragma unroll
        for (int k = 0; k < BK; k++) {
            float a[TM], bb[TN];
#pragma unroll
            for (int i = 0; i < TM; i++) a[i] = As[k][tr * TM + i];
#pragma unroll
            for (int j = 0; j < TN; j++) bb[j] = Bs[k][tc * TN + j];
#pragma unroll
            for (int i = 0; i < TM; i++)
#pragma unroll
                for (int j = 0; j < TN; j++)
                    acc[i][j] = fmaf(a[i], bb[j], acc[i][j]);
        }
        __syncthreads();
    }

    // Fused cosine epilogue
    const int nbase = tileN * BM + tr * TM;
    const int mbase = tileM * BN + tc * TN;
    const float* xnb = g_xn + b * Nq;
    const float* ynb = g_yn + b * Nq;

    float xv[TM], yv[TN];
#pragma unroll
    for (int i = 0; i < TM; i++) xv[i] = xnb[nbase + i];
#pragma unroll
    for (int j = 0; j < TN; j++) yv[j] = ynb[mbase + j];

    float* ob = out + (size_t)b * Nq * Nq;
#pragma unroll
    for (int i = 0; i < TM; i++) {
        float4 v0, v1;
        float r[TN];
#pragma unroll
        for (int j = 0; j < TN; j++) {
            float denom = fmaxf(xv[i] * yv[j], EPSq);
            r[j] = acc[i][j] / denom;
        }
        v0 = make_float4(r[0], r[1], r[2], r[3]);
        v1 = make_float4(r[4], r[5], r[6], r[7]);
        float* orow = ob + (size_t)(nbase + i) * Nq + mbase;
        *reinterpret_cast<float4*>(orow) = v0;
        *reinterpret_cast<float4*>(orow + 4) = v1;
    }
}

// ---------------------------------------------------------------------------
// Launch
// ---------------------------------------------------------------------------
extern "C" void kernel_launch(void* const* d_in, const int* in_sizes, int n_in,
                              void* d_out, int out_size) {
    const float* x = (const float*)d_in[0];
    const float* y = (const float*)d_in[1];
    float* out = (float*)d_out;

    // Norms: warp per row, 8 warps per block
    int total_rows = Bq * Nq;                       // 16384
    int norm_blocks = (total_rows + 7) / 8;         // 2048
    norms_kernel<<<norm_blocks, 256>>>(x, y);

    dim3 grid(Nq / BN, Nq / BM, Bq);                // (16, 16, 8)
    cosine_gemm_kernel<<<grid, 256>>>(x, y, out);
}

// round 3
// speedup vs baseline: 2.3347x; 2.3347x over previous
#include <cuda_runtime.h>
#include <cuda_bf16.h>
#include <cstdint>

// ============================================================================
// out[b,n,m] = <x[b,n,:], y[b,m,:]> / max(||x[b,n]|| * ||y[b,m]||, eps)
//   x, y: [8, 2048, 512] fp32 ; out: [8, 2048, 2048] fp32
//
// Round 3: compute_103-portable tensor path.
//   prep:  fp32 -> bf16 hi + bf16 lo (Markidis split) + row norms.
//   gemm:  mma.sync.m16n8k16 bf16, 3 passes (hi*hi + hi*lo + lo*hi) into fp32
//          accumulators; cp.async 3-stage pipeline; ldmatrix with XOR swizzle;
//          fused cosine epilogue.
// ============================================================================

#define Bq 8
#define Nq 2048
#define Dq 512
#define EPSq 1e-8f

#define BMq 128      // x rows per CTA
#define BNq 128      // y rows per CTA
#define BKq 64       // k per stage (64 bf16 = 128B row)
#define NSTAGE 3
#define KITER (Dq / BKq)          // 8

// per-stage smem: Ahi | Alo | Bhi | Blo, each 128 rows * 128B = 16 KB
#define OP_BYTES   16384
#define STG_BYTES  65536
#define SMEM_TOTAL (NSTAGE * STG_BYTES)   // 196608

__device__ float g_xn[Bq * Nq];
__device__ float g_yn[Bq * Nq];
__device__ __nv_bfloat16 g_xhi[Bq * Nq * Dq];
__device__ __nv_bfloat16 g_xlo[Bq * Nq * Dq];
__device__ __nv_bfloat16 g_yhi[Bq * Nq * Dq];
__device__ __nv_bfloat16 g_ylo[Bq * Nq * Dq];

// ---------------------------------------------------------------------------
__device__ __forceinline__ uint32_t smem_u32(const void* p) {
    uint32_t a;
    asm("{ .reg .u64 t; cvta.to.shared.u64 t, %1; cvt.u32.u64 %0, t; }"
        : "=r"(a) : "l"(p));
    return a;
}

#define CP_ASYNC16(dst, src) \
    asm volatile("cp.async.cg.shared.global [%0], [%1], 16;" \
                 :: "r"(dst), "l"(src) : "memory")
#define CP_COMMIT() asm volatile("cp.async.commit_group;" ::: "memory")
#define CP_WAIT1()  asm volatile("cp.async.wait_group 1;" ::: "memory")

#define LDSM4(r, addr) \
    asm volatile("ldmatrix.sync.aligned.m8n8.x4.shared.b16 {%0,%1,%2,%3}, [%4];" \
                 : "=r"((r)[0]), "=r"((r)[1]), "=r"((r)[2]), "=r"((r)[3]) \
                 : "r"(addr))

#define MMA16816(d, a, bf) \
    asm volatile("mma.sync.aligned.m16n8k16.row.col.f32.bf16.bf16.f32 " \
                 "{%0,%1,%2,%3}, {%4,%5,%6,%7}, {%8,%9}, {%0,%1,%2,%3};" \
                 : "+f"((d)[0]), "+f"((d)[1]), "+f"((d)[2]), "+f"((d)[3]) \
                 : "r"((a)[0]), "r"((a)[1]), "r"((a)[2]), "r"((a)[3]), \
                   "r"((bf)[0]), "r"((bf)[1]))

// ---------------------------------------------------------------------------
// Prep: one warp per row (x row + y row): norms + hi/lo bf16 split.
// ---------------------------------------------------------------------------
__global__ void __launch_bounds__(256) prep_kernel(const float* __restrict__ X,
                                                   const float* __restrict__ Y) {
    int row = blockIdx.x * 8 + (threadIdx.x >> 5);
    int lane = threadIdx.x & 31;
    if (row >= Bq * Nq) return;

    const float4* px = reinterpret_cast<const float4*>(X + (size_t)row * Dq);
    const float4* py = reinterpret_cast<const float4*>(Y + (size_t)row * Dq);

    float sx = 0.f, sy = 0.f;
#pragma unroll
    for (int v = 0; v < 4; v++) {
        int i = v * 32 + lane;
        {
            float4 a = px[i];
            sx = fmaf(a.x, a.x, sx); sx = fmaf(a.y, a.y, sx);
            sx = fmaf(a.z, a.z, sx); sx = fmaf(a.w, a.w, sx);
            __nv_bfloat162 h0 = __floats2bfloat162_rn(a.x, a.y);
            __nv_bfloat162 h1 = __floats2bfloat162_rn(a.z, a.w);
            __nv_bfloat162 l0 = __floats2bfloat162_rn(a.x - __bfloat162float(h0.x),
                                                      a.y - __bfloat162float(h0.y));
            __nv_bfloat162 l1 = __floats2bfloat162_rn(a.z - __bfloat162float(h1.x),
                                                      a.w - __bfloat162float(h1.y));
            size_t off = (size_t)row * Dq + (size_t)i * 4;
            *reinterpret_cast<__nv_bfloat162*>(g_xhi + off)     = h0;
            *reinterpret_cast<__nv_bfloat162*>(g_xhi + off + 2) = h1;
            *reinterpret_cast<__nv_bfloat162*>(g_xlo + off)     = l0;
            *reinterpret_cast<__nv_bfloat162*>(g_xlo + off + 2) = l1;
        }
        {
            float4 a = py[i];
            sy = fmaf(a.x, a.x, sy); sy = fmaf(a.y, a.y, sy);
            sy = fmaf(a.z, a.z, sy); sy = fmaf(a.w, a.w, sy);
            __nv_bfloat162 h0 = __floats2bfloat162_rn(a.x, a.y);
            __nv_bfloat162 h1 = __floats2bfloat162_rn(a.z, a.w);
            __nv_bfloat162 l0 = __floats2bfloat162_rn(a.x - __bfloat162float(h0.x),
                                                      a.y - __bfloat162float(h0.y));
            __nv_bfloat162 l1 = __floats2bfloat162_rn(a.z - __bfloat162float(h1.x),
                                                      a.w - __bfloat162float(h1.y));
            size_t off = (size_t)row * Dq + (size_t)i * 4;
            *reinterpret_cast<__nv_bfloat162*>(g_yhi + off)     = h0;
            *reinterpret_cast<__nv_bfloat162*>(g_yhi + off + 2) = h1;
            *reinterpret_cast<__nv_bfloat162*>(g_ylo + off)     = l0;
            *reinterpret_cast<__nv_bfloat162*>(g_ylo + off + 2) = l1;
        }
    }
#pragma unroll
    for (int off = 16; off > 0; off >>= 1) {
        sx += __shfl_xor_sync(0xFFFFFFFFu, sx, off);
        sy += __shfl_xor_sync(0xFFFFFFFFu, sy, off);
    }
    if (lane == 0) {
        g_xn[row] = sqrtf(sx);
        g_yn[row] = sqrtf(sy);
    }
}

// ---------------------------------------------------------------------------
// cp.async one pipeline stage: 4 operands x (128 rows x 8 chunks of 16B).
// smem layout per operand: row * 128B, chunk swizzled: c' = c ^ (row & 7).
// ---------------------------------------------------------------------------
__device__ __forceinline__ void load_stage(uint32_t sb_stage, int kt,
                                           int rowA0, int rowB0, int b, int tid) {
    const size_t kbase = (size_t)kt * BKq;
#pragma unroll
    for (int i = 0; i < 4; i++) {
        int idx = tid + i * 256;          // 0..1023
        int r = idx >> 3;                 // 0..127
        int c = idx & 7;                  // 16B chunk
        uint32_t doff = (uint32_t)r * 128 + (uint32_t)((c ^ (r & 7)) << 4);
        size_t offA = ((size_t)(b * Nq + rowA0 + r)) * Dq + kbase + c * 8;
        size_t offB = ((size_t)(b * Nq + rowB0 + r)) * Dq + kbase + c * 8;
        CP_ASYNC16(sb_stage + 0 * OP_BYTES + doff, g_xhi + offA);
        CP_ASYNC16(sb_stage + 1 * OP_BYTES + doff, g_xlo + offA);
        CP_ASYNC16(sb_stage + 2 * OP_BYTES + doff, g_yhi + offB);
        CP_ASYNC16(sb_stage + 3 * OP_BYTES + doff, g_ylo + offB);
    }
}

// ---------------------------------------------------------------------------
// GEMM kernel. Grid (16,16,8), 256 threads = 8 warps (2 x 4), warp tile 64x32.
// ---------------------------------------------------------------------------
__global__ void __launch_bounds__(256, 1) cosine_mma_kernel(float* __restrict__ out) {
    extern __shared__ char smem[];
    const uint32_t sb = smem_u32(smem);

    const int tid = threadIdx.x;
    const int wid = tid >> 5, lane = tid & 31;
    const int wm = wid >> 2;          // 0..1  (64 m-rows each)
    const int wn = wid & 3;           // 0..3  (32 n-cols each)
    const int tileM = blockIdx.x;     // y tile
    const int tileN = blockIdx.y;     // x tile
    const int b = blockIdx.z;
    const int rowA0 = tileN * BMq;
    const int rowB0 = tileM * BNq;

    float acc[4][4][4];
#pragma unroll
    for (int i = 0; i < 4; i++)
#pragma unroll
        for (int j = 0; j < 4; j++)
#pragma unroll
            for (int r = 0; r < 4; r++) acc[i][j][r] = 0.f;

    // prologue: stages 0, 1
    load_stage(sb + 0 * STG_BYTES, 0, rowA0, rowB0, b, tid); CP_COMMIT();
    load_stage(sb + 1 * STG_BYTES, 1, rowA0, rowB0, b, tid); CP_COMMIT();

    const int r8 = lane & 7;
    const int quad = lane >> 3;
    const int rowSel = r8 + ((quad & 1) << 3);   // 0..15 within 16-row tile
    const int kcq = quad >> 1;                   // 0/1: which k8-half chunk

    for (int t = 0; t < KITER; t++) {
        CP_WAIT1();
        __syncthreads();
        if (t + 2 < KITER)
            load_stage(sb + ((t + 2) % NSTAGE) * STG_BYTES, t + 2, rowA0, rowB0, b, tid);
        CP_COMMIT();

        const uint32_t st = sb + (t % NSTAGE) * STG_BYTES;
        const uint32_t sAhi = st, sAlo = st + OP_BYTES;
        const uint32_t sBhi = st + 2 * OP_BYTES, sBlo = st + 3 * OP_BYTES;

#pragma unroll
        for (int k16 = 0; k16 < BKq / 16; k16++) {
            const int kc = k16 * 2 + kcq;
            uint32_t a_hi[4][4], a_lo[4][4];
            uint32_t b_hi[4][2], b_lo[4][2];
#pragma unroll
            for (int mi = 0; mi < 4; mi++) {
                int row = wm * 64 + mi * 16 + rowSel;
                uint32_t off = (uint32_t)row * 128 + (uint32_t)((kc ^ (row & 7)) << 4);
                LDSM4(a_hi[mi], sAhi + off);
                LDSM4(a_lo[mi], sAlo + off);
            }
#pragma unroll
            for (int nj = 0; nj < 2; nj++) {
                int row = wn * 32 + nj * 16 + rowSel;
                uint32_t off = (uint32_t)row * 128 + (uint32_t)((kc ^ (row & 7)) << 4);
                uint32_t th[4], tl[4];
                LDSM4(th, sBhi + off);
                LDSM4(tl, sBlo + off);
                b_hi[2 * nj][0] = th[0]; b_hi[2 * nj + 1][0] = th[1];
                b_hi[2 * nj][1] = th[2]; b_hi[2 * nj + 1][1] = th[3];
                b_lo[2 * nj][0] = tl[0]; b_lo[2 * nj + 1][0] = tl[1];
                b_lo[2 * nj][1] = tl[2]; b_lo[2 * nj + 1][1] = tl[3];
            }
#pragma unroll
            for (int mi = 0; mi < 4; mi++)
#pragma unroll
                for (int ni = 0; ni < 4; ni++) {
                    MMA16816(acc[mi][ni], a_hi[mi], b_hi[ni]);
                    MMA16816(acc[mi][ni], a_hi[mi], b_lo[ni]);
                    MMA16816(acc[mi][ni], a_lo[mi], b_hi[ni]);
                }
        }
        __syncthreads();
    }

    // ---- fused cosine epilogue ----
    const int gq = lane >> 2;       // 0..7  (m within 8-row group)
    const int tq = lane & 3;        // 0..3  (n pair)

    float yv0[4], yv1[4];
#pragma unroll
    for (int ni = 0; ni < 4; ni++) {
        int n = rowB0 + wn * 32 + ni * 8 + 2 * tq;
        yv0[ni] = g_yn[b * Nq + n];
        yv1[ni] = g_yn[b * Nq + n + 1];
    }

#pragma unroll
    for (int mi = 0; mi < 4; mi++) {
        int mA = rowA0 + wm * 64 + mi * 16 + gq;
        float xA = g_xn[b * Nq + mA];
        float xB = g_xn[b * Nq + mA + 8];
        float* orowA = out + ((size_t)b * Nq + mA) * Nq + rowB0 + wn * 32;
        float* orowB = orowA + 8 * (size_t)Nq;
#pragma unroll
        for (int ni = 0; ni < 4; ni++) {
            float2 vA, vB;
            vA.x = acc[mi][ni][0] / fmaxf(xA * yv0[ni], EPSq);
            vA.y = acc[mi][ni][1] / fmaxf(xA * yv1[ni], EPSq);
            vB.x = acc[mi][ni][2] / fmaxf(xB * yv0[ni], EPSq);
            vB.y = acc[mi][ni][3] / fmaxf(xB * yv1[ni], EPSq);
            *reinterpret_cast<float2*>(orowA + ni * 8 + 2 * tq) = vA;
            *reinterpret_cast<float2*>(orowB + ni * 8 + 2 * tq) = vB;
        }
    }
}

// ---------------------------------------------------------------------------
extern "C" void kernel_launch(void* const* d_in, const int* in_sizes, int n_in,
                              void* d_out, int out_size) {
    const float* x = (const float*)d_in[0];
    const float* y = (const float*)d_in[1];
    float* out = (float*)d_out;

    prep_kernel<<<(Bq * Nq + 7) / 8, 256>>>(x, y);

    cudaFuncSetAttribute(cosine_mma_kernel,
                         cudaFuncAttributeMaxDynamicSharedMemorySize, SMEM_TOTAL);
    dim3 grid(Nq / BNq, Nq / BMq, Bq);   // (16, 16, 8)
    cosine_mma_kernel<<<grid, 256, SMEM_TOTAL>>>(out);
}

// round 4
// speedup vs baseline: 2.5857x; 1.1075x over previous
#include <cuda_runtime.h>
#include <cuda_bf16.h>
#include <cstdint>

// ============================================================================
// out[b,n,m] = <x[b,n,:], y[b,m,:]> / max(||x[b,n]|| * ||y[b,m]||, eps)
//   x, y: [8, 2048, 512] fp32 ; out: [8, 2048, 2048] fp32
//
// Round 4: same bf16 Markidis 3-pass mma.sync math as round 3, but:
//   - CTA tile 128x256, 512 threads (16 warps -> 4/SMSP, was 2/SMSP)
//   - 2-stage cp.async pipeline (96KB/stage)
//   - reduced live registers (A fragments loaded per-mi inside loop)
// ============================================================================

#define Bq 8
#define Nq 2048
#define Dq 512
#define EPSq 1e-8f

#define BMq 128      // x rows per CTA
#define BNq 256      // y rows per CTA
#define BKq 64       // k per stage (64 bf16 = 128B row)
#define NSTAGE 2
#define KITER (Dq / BKq)          // 8

// per-stage smem: Ahi 16K | Alo 16K | Bhi 32K | Blo 32K = 96KB
#define A_OP_BYTES 16384
#define B_OP_BYTES 32768
#define A_HI_OFF   0
#define A_LO_OFF   16384
#define B_HI_OFF   32768
#define B_LO_OFF   65536
#define STG_BYTES  98304
#define SMEM_TOTAL (NSTAGE * STG_BYTES)   // 196608

__device__ float g_xn[Bq * Nq];
__device__ float g_yn[Bq * Nq];
__device__ __nv_bfloat16 g_xhi[Bq * Nq * Dq];
__device__ __nv_bfloat16 g_xlo[Bq * Nq * Dq];
__device__ __nv_bfloat16 g_yhi[Bq * Nq * Dq];
__device__ __nv_bfloat16 g_ylo[Bq * Nq * Dq];

// ---------------------------------------------------------------------------
__device__ __forceinline__ uint32_t smem_u32(const void* p) {
    uint32_t a;
    asm("{ .reg .u64 t; cvta.to.shared.u64 t, %1; cvt.u32.u64 %0, t; }"
        : "=r"(a) : "l"(p));
    return a;
}

#define CP_ASYNC16(dst, src) \
    asm volatile("cp.async.cg.shared.global [%0], [%1], 16;" \
                 :: "r"(dst), "l"(src) : "memory")
#define CP_COMMIT() asm volatile("cp.async.commit_group;" ::: "memory")
#define CP_WAIT1()  asm volatile("cp.async.wait_group 1;" ::: "memory")

#define LDSM4(r, addr) \
    asm volatile("ldmatrix.sync.aligned.m8n8.x4.shared.b16 {%0,%1,%2,%3}, [%4];" \
                 : "=r"((r)[0]), "=r"((r)[1]), "=r"((r)[2]), "=r"((r)[3]) \
                 : "r"(addr))

#define MMA16816(d, a, bf) \
    asm volatile("mma.sync.aligned.m16n8k16.row.col.f32.bf16.bf16.f32 " \
                 "{%0,%1,%2,%3}, {%4,%5,%6,%7}, {%8,%9}, {%0,%1,%2,%3};" \
                 : "+f"((d)[0]), "+f"((d)[1]), "+f"((d)[2]), "+f"((d)[3]) \
                 : "r"((a)[0]), "r"((a)[1]), "r"((a)[2]), "r"((a)[3]), \
                   "r"((bf)[0]), "r"((bf)[1]))

// ---------------------------------------------------------------------------
// Prep: one warp per row (x row + y row): norms + hi/lo bf16 split.
// ---------------------------------------------------------------------------
__global__ void __launch_bounds__(256) prep_kernel(const float* __restrict__ X,
                                                   const float* __restrict__ Y) {
    int row = blockIdx.x * 8 + (threadIdx.x >> 5);
    int lane = threadIdx.x & 31;
    if (row >= Bq * Nq) return;

    const float4* px = reinterpret_cast<const float4*>(X + (size_t)row * Dq);
    const float4* py = reinterpret_cast<const float4*>(Y + (size_t)row * Dq);

    float sx = 0.f, sy = 0.f;
#pragma unroll
    for (int v = 0; v < 4; v++) {
        int i = v * 32 + lane;
        {
            float4 a = px[i];
            sx = fmaf(a.x, a.x, sx); sx = fmaf(a.y, a.y, sx);
            sx = fmaf(a.z, a.z, sx); sx = fmaf(a.w, a.w, sx);
            __nv_bfloat162 h0 = __floats2bfloat162_rn(a.x, a.y);
            __nv_bfloat162 h1 = __floats2bfloat162_rn(a.z, a.w);
            __nv_bfloat162 l0 = __floats2bfloat162_rn(a.x - __bfloat162float(h0.x),
                                                      a.y - __bfloat162float(h0.y));
            __nv_bfloat162 l1 = __floats2bfloat162_rn(a.z - __bfloat162float(h1.x),
                                                      a.w - __bfloat162float(h1.y));
            size_t off = (size_t)row * Dq + (size_t)i * 4;
            *reinterpret_cast<__nv_bfloat162*>(g_xhi + off)     = h0;
            *reinterpret_cast<__nv_bfloat162*>(g_xhi + off + 2) = h1;
            *reinterpret_cast<__nv_bfloat162*>(g_xlo + off)     = l0;
            *reinterpret_cast<__nv_bfloat162*>(g_xlo + off + 2) = l1;
        }
        {
            float4 a = py[i];
            sy = fmaf(a.x, a.x, sy); sy = fmaf(a.y, a.y, sy);
            sy = fmaf(a.z, a.z, sy); sy = fmaf(a.w, a.w, sy);
            __nv_bfloat162 h0 = __floats2bfloat162_rn(a.x, a.y);
            __nv_bfloat162 h1 = __floats2bfloat162_rn(a.z, a.w);
            __nv_bfloat162 l0 = __floats2bfloat162_rn(a.x - __bfloat162float(h0.x),
                                                      a.y - __bfloat162float(h0.y));
            __nv_bfloat162 l1 = __floats2bfloat162_rn(a.z - __bfloat162float(h1.x),
                                                      a.w - __bfloat162float(h1.y));
            size_t off = (size_t)row * Dq + (size_t)i * 4;
            *reinterpret_cast<__nv_bfloat162*>(g_yhi + off)     = h0;
            *reinterpret_cast<__nv_bfloat162*>(g_yhi + off + 2) = h1;
            *reinterpret_cast<__nv_bfloat162*>(g_ylo + off)     = l0;
            *reinterpret_cast<__nv_bfloat162*>(g_ylo + off + 2) = l1;
        }
    }
#pragma unroll
    for (int off = 16; off > 0; off >>= 1) {
        sx += __shfl_xor_sync(0xFFFFFFFFu, sx, off);
        sy += __shfl_xor_sync(0xFFFFFFFFu, sy, off);
    }
    if (lane == 0) {
        g_xn[row] = sqrtf(sx);
        g_yn[row] = sqrtf(sy);
    }
}

// ---------------------------------------------------------------------------
// cp.async one stage: A 128 rows (hi+lo), B 256 rows (hi+lo), 128B rows,
// chunk swizzle c' = c ^ (row & 7). 512 threads.
// ---------------------------------------------------------------------------
__device__ __forceinline__ void load_stage(uint32_t sb_stage, int kt,
                                           int rowA0, int rowB0, int b, int tid) {
    const size_t kbase = (size_t)kt * BKq;
    // A: 128 rows x 8 chunks = 1024 chunks per operand
#pragma unroll
    for (int i = 0; i < 2; i++) {
        int idx = tid + i * 512;          // 0..1023
        int r = idx >> 3;
        int c = idx & 7;
        uint32_t doff = (uint32_t)r * 128 + (uint32_t)((c ^ (r & 7)) << 4);
        size_t off = ((size_t)(b * Nq + rowA0 + r)) * Dq + kbase + c * 8;
        CP_ASYNC16(sb_stage + A_HI_OFF + doff, g_xhi + off);
        CP_ASYNC16(sb_stage + A_LO_OFF + doff, g_xlo + off);
    }
    // B: 256 rows x 8 chunks = 2048 chunks per operand
#pragma unroll
    for (int i = 0; i < 4; i++) {
        int idx = tid + i * 512;          // 0..2047
        int r = idx >> 3;
        int c = idx & 7;
        uint32_t doff = (uint32_t)r * 128 + (uint32_t)((c ^ (r & 7)) << 4);
        size_t off = ((size_t)(b * Nq + rowB0 + r)) * Dq + kbase + c * 8;
        CP_ASYNC16(sb_stage + B_HI_OFF + doff, g_yhi + off);
        CP_ASYNC16(sb_stage + B_LO_OFF + doff, g_ylo + off);
    }
}

// ---------------------------------------------------------------------------
// GEMM kernel. Grid (8,16,8), 512 threads = 16 warps (2 x 8), warp tile 64x32.
// ---------------------------------------------------------------------------
__global__ void __launch_bounds__(512, 1) cosine_mma_kernel(float* __restrict__ out) {
    extern __shared__ char smem[];
    const uint32_t sb = smem_u32(smem);

    const int tid = threadIdx.x;
    const int wid = tid >> 5, lane = tid & 31;
    const int wm = wid >> 3;          // 0..1  (64 m-rows each)
    const int wn = wid & 7;           // 0..7  (32 n-cols each)
    const int tileM = blockIdx.x;     // y tile (256 rows)
    const int tileN = blockIdx.y;     // x tile (128 rows)
    const int b = blockIdx.z;
    const int rowA0 = tileN * BMq;
    const int rowB0 = tileM * BNq;

    float acc[4][4][4];
#pragma unroll
    for (int i = 0; i < 4; i++)
#pragma unroll
        for (int j = 0; j < 4; j++)
#pragma unroll
            for (int r = 0; r < 4; r++) acc[i][j][r] = 0.f;

    // prologue
    load_stage(sb + 0 * STG_BYTES, 0, rowA0, rowB0, b, tid); CP_COMMIT();
    load_stage(sb + 1 * STG_BYTES, 1, rowA0, rowB0, b, tid); CP_COMMIT();

    const int r8 = lane & 7;
    const int quad = lane >> 3;
    const int rowSel = r8 + ((quad & 1) << 3);   // 0..15 within 16-row tile
    const int kcq = quad >> 1;                   // 0/1: which 16B chunk half

    // hoisted per-lane address pieces
    uint32_t aRowTerm[4], aSwz[4];
#pragma unroll
    for (int mi = 0; mi < 4; mi++) {
        int row = wm * 64 + mi * 16 + rowSel;
        aRowTerm[mi] = (uint32_t)row * 128;
        aSwz[mi] = (uint32_t)(row & 7) << 4;
    }
    uint32_t bRowTerm[2], bSwz[2];
#pragma unroll
    for (int nj = 0; nj < 2; nj++) {
        int row = wn * 32 + nj * 16 + rowSel;
        bRowTerm[nj] = (uint32_t)row * 128;
        bSwz[nj] = (uint32_t)(row & 7) << 4;
    }

    for (int t = 0; t < KITER; t++) {
        CP_WAIT1();
        __syncthreads();

        const uint32_t st = sb + (t & 1) * STG_BYTES;
        const uint32_t sAhi = st + A_HI_OFF, sAlo = st + A_LO_OFF;
        const uint32_t sBhi = st + B_HI_OFF, sBlo = st + B_LO_OFF;

#pragma unroll
        for (int k16 = 0; k16 < BKq / 16; k16++) {
            const uint32_t kterm = (uint32_t)(k16 * 2 + kcq) << 4;
            // B fragments for this k16 (kept live across mi loop)
            uint32_t b_hi[4][2], b_lo[4][2];
#pragma unroll
            for (int nj = 0; nj < 2; nj++) {
                uint32_t off = bRowTerm[nj] + (kterm ^ bSwz[nj]);
                uint32_t th[4], tl[4];
                LDSM4(th, sBhi + off);
                LDSM4(tl, sBlo + off);
                b_hi[2 * nj][0] = th[0]; b_hi[2 * nj + 1][0] = th[1];
                b_hi[2 * nj][1] = th[2]; b_hi[2 * nj + 1][1] = th[3];
                b_lo[2 * nj][0] = tl[0]; b_lo[2 * nj + 1][0] = tl[1];
                b_lo[2 * nj][1] = tl[2]; b_lo[2 * nj + 1][1] = tl[3];
            }
#pragma unroll
            for (int mi = 0; mi < 4; mi++) {
                uint32_t a_hi[4], a_lo[4];
                uint32_t off = aRowTerm[mi] + (kterm ^ aSwz[mi]);
                LDSM4(a_hi, sAhi + off);
                LDSM4(a_lo, sAlo + off);
#pragma unroll
                for (int ni = 0; ni < 4; ni++) {
                    MMA16816(acc[mi][ni], a_hi, b_hi[ni]);
                    MMA16816(acc[mi][ni], a_hi, b_lo[ni]);
                    MMA16816(acc[mi][ni], a_lo, b_hi[ni]);
                }
            }
        }
        __syncthreads();
        if (t + 2 < KITER)
            load_stage(sb + (t & 1) * STG_BYTES, t + 2, rowA0, rowB0, b, tid);
        CP_COMMIT();
    }

    // ---- fused cosine epilogue ----
    const int gq = lane >> 2;       // 0..7  (m within 8-row group)
    const int tq = lane & 3;        // 0..3  (n pair)

    float yv0[4], yv1[4];
#pragma unroll
    for (int ni = 0; ni < 4; ni++) {
        int n = rowB0 + wn * 32 + ni * 8 + 2 * tq;
        yv0[ni] = g_yn[b * Nq + n];
        yv1[ni] = g_yn[b * Nq + n + 1];
    }

#pragma unroll
    for (int mi = 0; mi < 4; mi++) {
        int mA = rowA0 + wm * 64 + mi * 16 + gq;
        float xA = g_xn[b * Nq + mA];
        float xB = g_xn[b * Nq + mA + 8];
        float* orowA = out + ((size_t)b * Nq + mA) * Nq + rowB0 + wn * 32;
        float* orowB = orowA + 8 * (size_t)Nq;
#pragma unroll
        for (int ni = 0; ni < 4; ni++) {
            float2 vA, vB;
            vA.x = acc[mi][ni][0] / fmaxf(xA * yv0[ni], EPSq);
            vA.y = acc[mi][ni][1] / fmaxf(xA * yv1[ni], EPSq);
            vB.x = acc[mi][ni][2] / fmaxf(xB * yv0[ni], EPSq);
            vB.y = acc[mi][ni][3] / fmaxf(xB * yv1[ni], EPSq);
            *reinterpret_cast<float2*>(orowA + ni * 8 + 2 * tq) = vA;
            *reinterpret_cast<float2*>(orowB + ni * 8 + 2 * tq) = vB;
        }
    }
}

// ---------------------------------------------------------------------------
extern "C" void kernel_launch(void* const* d_in, const int* in_sizes, int n_in,
                              void* d_out, int out_size) {
    const float* x = (const float*)d_in[0];
    const float* y = (const float*)d_in[1];
    float* out = (float*)d_out;

    prep_kernel<<<(Bq * Nq + 7) / 8, 256>>>(x, y);

    cudaFuncSetAttribute(cosine_mma_kernel,
                         cudaFuncAttributeMaxDynamicSharedMemorySize, SMEM_TOTAL);
    dim3 grid(Nq / BNq, Nq / BMq, Bq);   // (8, 16, 8)
    cosine_mma_kernel<<<grid, 512, SMEM_TOTAL>>>(out);
}